// round 6
// baseline (speedup 1.0000x reference)
#include <cuda_runtime.h>
#include <cuda_fp16.h>
#include <cstdint>

#define N_NODES 100000
#define FT_IN   128
#define NHID    64
#define N_EDGES 1000000
#define PDIM    128
#define KSTR    136            // padded k-stride in halves -> 272 B rows

// ---------------------------------------------------------------------------
// Device scratch
// ---------------------------------------------------------------------------
__device__ __half g_Ph[(size_t)N_NODES * PDIM];          // 25.6 MB, L2-resident
__device__ __align__(16) __half g_Bh[PDIM * KSTR];       // B[n][k] fp16 (padded)
__device__ float g_beff[NHID];
__device__ int g_flag;                                   // B-ready flag (0-init)
__device__ int g_done;                                   // completion counter

// ---------------------------------------------------------------------------
// PTX helpers (compute_100-legal)
// ---------------------------------------------------------------------------
__device__ __forceinline__ uint32_t smem_u32(const void* p) {
    uint32_t a;
    asm("{ .reg .u64 t; cvta.to.shared.u64 t, %1; cvt.u32.u64 %0, t; }" : "=r"(a) : "l"(p));
    return a;
}
__device__ __forceinline__ void ldsm_x4(uint32_t* r, uint32_t a) {
    asm volatile("ldmatrix.sync.aligned.m8n8.x4.shared.b16 {%0,%1,%2,%3}, [%4];"
                 : "=r"(r[0]), "=r"(r[1]), "=r"(r[2]), "=r"(r[3]) : "r"(a));
}
__device__ __forceinline__ void ldsm_x2(uint32_t* r, uint32_t a) {
    asm volatile("ldmatrix.sync.aligned.m8n8.x2.shared.b16 {%0,%1}, [%2];"
                 : "=r"(r[0]), "=r"(r[1]) : "r"(a));
}
__device__ __forceinline__ void mma_f16(float* d, const uint32_t* a, const uint32_t* b) {
    asm volatile("mma.sync.aligned.m16n8k16.row.col.f32.f16.f16.f32 "
                 "{%0,%1,%2,%3}, {%4,%5,%6,%7}, {%8,%9}, {%0,%1,%2,%3};"
                 : "+f"(d[0]), "+f"(d[1]), "+f"(d[2]), "+f"(d[3])
                 : "r"(a[0]), "r"(a[1]), "r"(a[2]), "r"(a[3]), "r"(b[0]), "r"(b[1]));
}

// ---------------------------------------------------------------------------
// Fused GEMM: CTA 0 first materializes B = W1cat @ W_enc (fp32->fp16) + beff,
// publishes via flag; all CTAs stage A meanwhile, then run
// P[100000,128] = seq @ B^T via mma.sync fp16, A split hi/lo (2 combos).
// CTA: 64 rows x 128 cols, 8 warps (2M x 4N), warp tile 32x32. 68KB smem.
// ---------------------------------------------------------------------------
#define SM_AHI 0
#define SM_ALO 17408
#define SM_BHI 34816
#define SM_TOTAL 69632
#define EPI_STR 272            // epilogue smem tile row stride (bytes)

__global__ __launch_bounds__(256, 3) void gemm_kernel(const float* __restrict__ seq,
                                                      const float* __restrict__ W_enc,
                                                      const float* __restrict__ W1,
                                                      const float* __restrict__ b_enc,
                                                      const float* __restrict__ b1) {
    extern __shared__ unsigned char sm[];
    const uint32_t sb = smem_u32(sm);
    const int tid = threadIdx.x;
    const int rowBase = blockIdx.x * 64;

    // ---- CTA 0: compute B (fp32) and publish --------------------------------
    if (blockIdx.x == 0) {
        float* smW1 = (float*)sm;                 // [j][n] : 64 x 128 fp32 (32KB)
        float* smWe = (float*)(sm + SM_BHI);      // [j][c] : 64 x 128 fp32 (32KB)
        for (int i = tid; i < NHID * 128; i += 256) {
            const int j = i >> 7, n = i & 127;
            smW1[j * 128 + n] = (n < NHID) ? W1[n * (2 * NHID) + j]
                                           : W1[(n - NHID) * (2 * NHID) + NHID + j];
            smWe[i] = W_enc[i];                   // straight copy [j][c]
        }
        __syncthreads();

        const int n = tid >> 1;
        const int cb = (tid & 1) * 64;
#pragma unroll
        for (int cc = 0; cc < 4; cc++) {
            float acc16[16];
#pragma unroll
            for (int q = 0; q < 16; q++) acc16[q] = 0.f;
#pragma unroll 8
            for (int j = 0; j < NHID; j++) {
                const float a = smW1[j * 128 + n];
                const float* br = smWe + j * 128 + cb + cc * 16;
#pragma unroll
                for (int q = 0; q < 16; q++) acc16[q] = fmaf(a, br[q], acc16[q]);
            }
#pragma unroll
            for (int q = 0; q < 16; q++)
                g_Bh[n * KSTR + cb + cc * 16 + q] = __float2half_rn(acc16[q]);
        }

        if (tid < NHID) {       // effective bias (uses smW1 [j][n])
            float t = b1[tid];
#pragma unroll 8
            for (int j = 0; j < NHID; j++) {
                const float be = b_enc[j];
                t = fmaf(smW1[j * 128 + tid],        be, t);
                t = fmaf(smW1[j * 128 + NHID + tid], be, t);
            }
            g_beff[tid] = t;
        }

        __threadfence();
        __syncthreads();
        if (tid == 0) atomicExch(&g_flag, 1);
        __syncthreads();        // smem regions free for reuse below
    }

    // ---- All CTAs: stage A (doesn't need B) ---------------------------------
    {
        const int rowm = tid >> 2;            // 0..63
        const int q    = tid & 3;             // 32-float quarter
        int g = rowBase + rowm; if (g > N_NODES - 1) g = N_NODES - 1;
        const float* src = seq + (size_t)g * FT_IN + q * 32;
        const int db = rowm * (KSTR * 2) + q * 64;    // bytes
#pragma unroll
        for (int i = 0; i < 4; i++) {         // 4 groups of 8 floats
            float4 v0 = *(const float4*)(src + i * 8);
            float4 v1 = *(const float4*)(src + i * 8 + 4);
            float f[8] = {v0.x, v0.y, v0.z, v0.w, v1.x, v1.y, v1.z, v1.w};
            uint32_t hi[4], lo[4];
#pragma unroll
            for (int p = 0; p < 4; p++) {
                float a = f[2 * p], b = f[2 * p + 1];
                __half2 h = __floats2half2_rn(a, b);
                float2 hf = __half22float2(h);
                __half2 l = __floats2half2_rn(a - hf.x, b - hf.y);
                hi[p] = *(uint32_t*)&h;
                lo[p] = *(uint32_t*)&l;
            }
            *(uint4*)(sm + SM_AHI + db + i * 16) = make_uint4(hi[0], hi[1], hi[2], hi[3]);
            *(uint4*)(sm + SM_ALO + db + i * 16) = make_uint4(lo[0], lo[1], lo[2], lo[3]);
        }
    }

    // ---- Wait for B, then copy to smem --------------------------------------
    if (tid == 0) {
        while (atomicAdd(&g_flag, 0) == 0) { }
        __threadfence();
    }
    __syncthreads();
    {
        const uint4* s4 = (const uint4*)g_Bh;
        uint4* d4 = (uint4*)(sm + SM_BHI);
#pragma unroll 3
        for (int i = tid; i < PDIM * KSTR * 2 / 16; i += 256) d4[i] = s4[i];
    }
    __syncthreads();

    // ---- Mainloop -----------------------------------------------------------
    const int warp = tid >> 5, lane = tid & 31;
    const int wM = warp & 1, wN = warp >> 1;      // 2 x 4 warp grid, tile 32x32

    float acc[2][4][4];
#pragma unroll
    for (int mt = 0; mt < 2; mt++)
#pragma unroll
        for (int nt = 0; nt < 4; nt++)
#pragma unroll
            for (int q = 0; q < 4; q++) acc[mt][nt][q] = 0.f;

    const uint32_t aAddr = sb + SM_AHI + (uint32_t)((wM * 32 + (lane & 15)) * (KSTR * 2)
                                                    + ((lane >> 4) << 3) * 2);
    const uint32_t bAddr = sb + SM_BHI + (uint32_t)((wN * 32 + (lane & 7)) * (KSTR * 2)
                                                    + (((lane >> 3) & 1) << 3) * 2);

#pragma unroll
    for (int k0 = 0; k0 < FT_IN; k0 += 16) {
        uint32_t ah[2][4], al[2][4], bh[4][2];
#pragma unroll
        for (int mt = 0; mt < 2; mt++) {
            uint32_t a = aAddr + mt * 16 * (KSTR * 2) + k0 * 2;
            ldsm_x4(ah[mt], a);
            ldsm_x4(al[mt], a + (SM_ALO - SM_AHI));
        }
#pragma unroll
        for (int nt = 0; nt < 4; nt++)
            ldsm_x2(bh[nt], bAddr + nt * 8 * (KSTR * 2) + k0 * 2);
#pragma unroll
        for (int mt = 0; mt < 2; mt++)
#pragma unroll
            for (int nt = 0; nt < 4; nt++) {
                mma_f16(acc[mt][nt], ah[mt], bh[nt]);   // Ahi * B
                mma_f16(acc[mt][nt], al[mt], bh[nt]);   // Alo * B
            }
    }
    __syncthreads();      // A region reused as epilogue tile

    // ---- Epilogue: fp32 acc -> fp16 via smem, coalesced to g_Ph -------------
    {
        unsigned char* tile = sm;   // reuse SM_AHI region
        const int r0 = wM * 32 + (lane >> 2);
        const int c0 = wN * 32 + (lane & 3) * 2;
#pragma unroll
        for (int mt = 0; mt < 2; mt++)
#pragma unroll
            for (int nt = 0; nt < 4; nt++) {
                const int col = c0 + nt * 8;
                __half2 lo2 = __floats2half2_rn(acc[mt][nt][0], acc[mt][nt][1]);
                __half2 hi2 = __floats2half2_rn(acc[mt][nt][2], acc[mt][nt][3]);
                *(__half2*)(tile + (r0 + mt * 16)     * EPI_STR + col * 2) = lo2;
                *(__half2*)(tile + (r0 + mt * 16 + 8) * EPI_STR + col * 2) = hi2;
            }
    }
    __syncthreads();
    {
        const int rowm = tid >> 2;
        const int seg  = tid & 3;
        const int grow = rowBase + rowm;
        if (grow < N_NODES) {
            const uint4* s4 = (const uint4*)(sm + rowm * EPI_STR + seg * 64);
            uint4* d4 = (uint4*)((unsigned char*)g_Ph + (size_t)grow * 256 + seg * 64);
#pragma unroll
            for (int i = 0; i < 4; i++) d4[i] = s4[i];
        }
    }

    // ---- Reset handshake (last CTA to finish) -------------------------------
    if (tid == 0) {
        __threadfence();
        const int d = atomicAdd(&g_done, 1);
        if (d == (int)gridDim.x - 1) {
            atomicExch(&g_flag, 0);
            atomicExch(&g_done, 0);
        }
    }
}

// ---------------------------------------------------------------------------
// Edge kernel: 8 lanes per edge (4 edges/warp). u,v = 16B/lane, 128B coalesced.
// ---------------------------------------------------------------------------
__global__ __launch_bounds__(256) void edge_kernel(const int* __restrict__ row,
                                                   const int* __restrict__ col,
                                                   const float* __restrict__ W2,
                                                   const float* __restrict__ b2,
                                                   float* __restrict__ out) {
    const int gt  = blockIdx.x * 256 + threadIdx.x;
    const int e   = gt >> 3;
    const int sub = gt & 7;
    if (e >= N_EDGES) return;

    const int r = __ldg(row + e);
    const int c = __ldg(col + e);

    const uint4 ur = *(const uint4*)(g_Ph + (size_t)r * PDIM + sub * 8);
    const uint4 vr = *(const uint4*)(g_Ph + (size_t)c * PDIM + NHID + sub * 8);
    const float4 be0 = *(const float4*)(g_beff + sub * 8);
    const float4 be1 = *(const float4*)(g_beff + sub * 8 + 4);
    const float4 w0  = *(const float4*)(W2 + sub * 8);
    const float4 w1  = *(const float4*)(W2 + sub * 8 + 4);

    const __half2* uh = (const __half2*)&ur;
    const __half2* vh = (const __half2*)&vr;
    const float be[8] = {be0.x, be0.y, be0.z, be0.w, be1.x, be1.y, be1.z, be1.w};
    const float w[8]  = {w0.x,  w0.y,  w0.z,  w0.w,  w1.x,  w1.y,  w1.z,  w1.w};

    float acc = 0.f;
#pragma unroll
    for (int i = 0; i < 4; i++) {
        const float2 uf = __half22float2(uh[i]);
        const float2 vf = __half22float2(vh[i]);
        const float h0 = fmaxf(uf.x + vf.x + be[2 * i],     0.f);
        const float h1 = fmaxf(uf.y + vf.y + be[2 * i + 1], 0.f);
        acc = fmaf(h0, w[2 * i],     acc);
        acc = fmaf(h1, w[2 * i + 1], acc);
    }

#pragma unroll
    for (int o = 4; o; o >>= 1) acc += __shfl_xor_sync(0xffffffffu, acc, o, 8);

    if (sub == 0) out[e] = acc + __ldg(b2);
}

// ---------------------------------------------------------------------------
extern "C" void kernel_launch(void* const* d_in, const int* in_sizes, int n_in,
                              void* d_out, int out_size) {
    const float* seq   = (const float*)d_in[0];
    const float* W_enc = (const float*)d_in[1];
    const float* b_enc = (const float*)d_in[2];
    const float* W1    = (const float*)d_in[3];
    const float* b1    = (const float*)d_in[4];
    const float* W2    = (const float*)d_in[5];
    const float* b2    = (const float*)d_in[6];
    const int*   rowi  = (const int*)d_in[7];
    const int*   coli  = (const int*)d_in[8];
    float* out = (float*)d_out;

    cudaFuncSetAttribute(gemm_kernel, cudaFuncAttributeMaxDynamicSharedMemorySize, SM_TOTAL);
    gemm_kernel<<<(N_NODES + 63) / 64, 256, SM_TOTAL>>>(seq, W_enc, W1, b_enc, b1);

    edge_kernel<<<(N_EDGES * 8 + 255) / 256, 256>>>(rowi, coli, W2, b2, out);
}

// round 8
// speedup vs baseline: 1.6482x; 1.6482x over previous
#include <cuda_runtime.h>
#include <cuda_fp16.h>
#include <cstdint>

#define N_NODES 100000
#define FT_IN   128
#define NHID    64
#define N_EDGES 1000000
#define PDIM    128
#define KSTR    136            // padded k-stride in halves -> 272 B rows

// ---------------------------------------------------------------------------
// Device scratch
// ---------------------------------------------------------------------------
__device__ __half g_Ph[(size_t)N_NODES * PDIM];          // 25.6 MB, L2-resident
__device__ __align__(16) __half g_Bh[PDIM * KSTR];       // B[n][k] fp16 (padded)
__device__ float g_beff[NHID];

// ---------------------------------------------------------------------------
// PTX helpers (compute_100-legal)
// ---------------------------------------------------------------------------
__device__ __forceinline__ uint32_t smem_u32(const void* p) {
    uint32_t a;
    asm("{ .reg .u64 t; cvta.to.shared.u64 t, %1; cvt.u32.u64 %0, t; }" : "=r"(a) : "l"(p));
    return a;
}
__device__ __forceinline__ void ldsm_x4(uint32_t* r, uint32_t a) {
    asm volatile("ldmatrix.sync.aligned.m8n8.x4.shared.b16 {%0,%1,%2,%3}, [%4];"
                 : "=r"(r[0]), "=r"(r[1]), "=r"(r[2]), "=r"(r[3]) : "r"(a));
}
__device__ __forceinline__ void ldsm_x2(uint32_t* r, uint32_t a) {
    asm volatile("ldmatrix.sync.aligned.m8n8.x2.shared.b16 {%0,%1}, [%2];"
                 : "=r"(r[0]), "=r"(r[1]) : "r"(a));
}
__device__ __forceinline__ void mma_f16(float* d, const uint32_t* a, const uint32_t* b) {
    asm volatile("mma.sync.aligned.m16n8k16.row.col.f32.f16.f16.f32 "
                 "{%0,%1,%2,%3}, {%4,%5,%6,%7}, {%8,%9}, {%0,%1,%2,%3};"
                 : "+f"(d[0]), "+f"(d[1]), "+f"(d[2]), "+f"(d[3])
                 : "r"(a[0]), "r"(a[1]), "r"(a[2]), "r"(a[3]), "r"(b[0]), "r"(b[1]));
}

// ---------------------------------------------------------------------------
// Prep: B[n][c] = sum_j W1row(n)[j] * W_enc[j][c]; fp16, padded [n][k].
// ---------------------------------------------------------------------------
__global__ __launch_bounds__(128) void prep_kernel(const float* __restrict__ W_enc,
                                                   const float* __restrict__ W1,
                                                   const float* __restrict__ b_enc,
                                                   const float* __restrict__ b1) {
    const int n = blockIdx.x;
    const int c = threadIdx.x;
    __shared__ float ws[NHID];
    if (c < NHID) {
        const float* w1row = (n < NHID) ? (W1 + (size_t)n * (2 * NHID))
                                        : (W1 + (size_t)(n - NHID) * (2 * NHID) + NHID);
        ws[c] = w1row[c];
    }
    __syncthreads();

    float s = 0.f;
#pragma unroll
    for (int j = 0; j < NHID; j++) s = fmaf(ws[j], W_enc[j * FT_IN + c], s);

    g_Bh[n * KSTR + c] = __float2half_rn(s);

    if (n == 0 && c < NHID) {
        const float* r = W1 + (size_t)c * (2 * NHID);
        float t = b1[c];
#pragma unroll
        for (int j = 0; j < NHID; j++) t = fmaf(r[j],        b_enc[j], t);
#pragma unroll
        for (int j = 0; j < NHID; j++) t = fmaf(r[NHID + j], b_enc[j], t);
        g_beff[c] = t;
    }
}

// ---------------------------------------------------------------------------
// GEMM: P[100000,128] = seq @ B^T via mma.sync fp16, A split hi/lo (2 combos).
// beff baked into cols 0..63 in the epilogue.
// CTA: 64 rows x 128 cols, 8 warps (2M x 4N), warp tile 32x32. 68KB smem.
// ---------------------------------------------------------------------------
#define SM_AHI 0
#define SM_ALO 17408
#define SM_BHI 34816
#define SM_TOTAL 69632
#define EPI_STR 272            // epilogue smem tile row stride (bytes)

__global__ __launch_bounds__(256, 2) void gemm_kernel(const float* __restrict__ seq) {
    extern __shared__ unsigned char sm[];
    const uint32_t sb = smem_u32(sm);
    const int tid = threadIdx.x;
    const int rowBase = blockIdx.x * 64;

    // Stage B (linear copy of padded image; L2-hot broadcast data)
    {
        const uint4* s4 = (const uint4*)g_Bh;
        uint4* d4 = (uint4*)(sm + SM_BHI);
#pragma unroll 3
        for (int i = tid; i < PDIM * KSTR * 2 / 16; i += 256) d4[i] = s4[i];
    }

    // Stage A: 64 rows x 128 fp32 -> fp16 hi/lo, 4 threads/row (32 floats each)
    {
        const int rowm = tid >> 2;            // 0..63
        const int q    = tid & 3;             // 32-float quarter
        int g = rowBase + rowm; if (g > N_NODES - 1) g = N_NODES - 1;
        const float* src = seq + (size_t)g * FT_IN + q * 32;
        const int db = rowm * (KSTR * 2) + q * 64;    // bytes
#pragma unroll
        for (int i = 0; i < 4; i++) {         // 4 groups of 8 floats
            float4 v0 = *(const float4*)(src + i * 8);
            float4 v1 = *(const float4*)(src + i * 8 + 4);
            float f[8] = {v0.x, v0.y, v0.z, v0.w, v1.x, v1.y, v1.z, v1.w};
            uint32_t hi[4], lo[4];
#pragma unroll
            for (int p = 0; p < 4; p++) {
                float a = f[2 * p], b = f[2 * p + 1];
                __half2 h = __floats2half2_rn(a, b);
                float2 hf = __half22float2(h);
                __half2 l = __floats2half2_rn(a - hf.x, b - hf.y);
                hi[p] = *(uint32_t*)&h;
                lo[p] = *(uint32_t*)&l;
            }
            *(uint4*)(sm + SM_AHI + db + i * 16) = make_uint4(hi[0], hi[1], hi[2], hi[3]);
            *(uint4*)(sm + SM_ALO + db + i * 16) = make_uint4(lo[0], lo[1], lo[2], lo[3]);
        }
    }
    __syncthreads();

    const int warp = tid >> 5, lane = tid & 31;
    const int wM = warp & 1, wN = warp >> 1;      // 2 x 4 warp grid, tile 32x32

    float acc[2][4][4];
#pragma unroll
    for (int mt = 0; mt < 2; mt++)
#pragma unroll
        for (int nt = 0; nt < 4; nt++)
#pragma unroll
            for (int q = 0; q < 4; q++) acc[mt][nt][q] = 0.f;

    const uint32_t aAddr = sb + SM_AHI + (uint32_t)((wM * 32 + (lane & 15)) * (KSTR * 2)
                                                    + ((lane >> 4) << 3) * 2);
    const uint32_t bAddr = sb + SM_BHI + (uint32_t)((wN * 32 + (lane & 7)) * (KSTR * 2)
                                                    + (((lane >> 3) & 1) << 3) * 2);

#pragma unroll
    for (int k0 = 0; k0 < FT_IN; k0 += 16) {
        uint32_t ah[2][4], al[2][4], bh[4][2];
#pragma unroll
        for (int mt = 0; mt < 2; mt++) {
            uint32_t a = aAddr + mt * 16 * (KSTR * 2) + k0 * 2;
            ldsm_x4(ah[mt], a);
            ldsm_x4(al[mt], a + (SM_ALO - SM_AHI));
        }
#pragma unroll
        for (int nt = 0; nt < 4; nt++)
            ldsm_x2(bh[nt], bAddr + nt * 8 * (KSTR * 2) + k0 * 2);
#pragma unroll
        for (int mt = 0; mt < 2; mt++)
#pragma unroll
            for (int nt = 0; nt < 4; nt++) {
                mma_f16(acc[mt][nt], ah[mt], bh[nt]);   // Ahi * B
                mma_f16(acc[mt][nt], al[mt], bh[nt]);   // Alo * B
            }
    }

    // Bias: bake beff into cols 0..63 (the "u" half)
    const int c0 = wN * 32 + (lane & 3) * 2;
    if (wN < 2) {
#pragma unroll
        for (int nt = 0; nt < 4; nt++) {
            const float2 be = *(const float2*)(g_beff + c0 + nt * 8);
#pragma unroll
            for (int mt = 0; mt < 2; mt++) {
                acc[mt][nt][0] += be.x;  acc[mt][nt][1] += be.y;
                acc[mt][nt][2] += be.x;  acc[mt][nt][3] += be.y;
            }
        }
    }
    __syncthreads();      // A region reused as epilogue tile

    // Epilogue: fp32 acc -> fp16, stage in smem [64][128] halves (stride 272B)
    {
        unsigned char* tile = sm;   // reuse SM_AHI region
        const int r0 = wM * 32 + (lane >> 2);
#pragma unroll
        for (int mt = 0; mt < 2; mt++)
#pragma unroll
            for (int nt = 0; nt < 4; nt++) {
                const int col = c0 + nt * 8;
                __half2 lo2 = __floats2half2_rn(acc[mt][nt][0], acc[mt][nt][1]);
                __half2 hi2 = __floats2half2_rn(acc[mt][nt][2], acc[mt][nt][3]);
                *(__half2*)(tile + (r0 + mt * 16)     * EPI_STR + col * 2) = lo2;
                *(__half2*)(tile + (r0 + mt * 16 + 8) * EPI_STR + col * 2) = hi2;
            }
    }
    __syncthreads();

    // Coalesced copy to g_Ph: 64 rows x 256B
    {
        const int rowm = tid >> 2;
        const int seg  = tid & 3;
        const int grow = rowBase + rowm;
        if (grow < N_NODES) {
            const uint4* s4 = (const uint4*)(sm + rowm * EPI_STR + seg * 64);
            uint4* d4 = (uint4*)((unsigned char*)g_Ph + (size_t)grow * 256 + seg * 64);
#pragma unroll
            for (int i = 0; i < 4; i++) d4[i] = s4[i];
        }
    }
}

// ---------------------------------------------------------------------------
// Edge kernel: 8-lane group processes 8 edges (1 thread per edge overall).
// W2 hoisted; row/col coalesced + width-8 shfl broadcast; per edge only the
// 2 irreducible 128B gathers.
// ---------------------------------------------------------------------------
__global__ __launch_bounds__(256) void edge_kernel(const int* __restrict__ row,
                                                   const int* __restrict__ col,
                                                   const float* __restrict__ W2,
                                                   const float* __restrict__ b2,
                                                   float* __restrict__ out) {
    const int t   = blockIdx.x * 256 + threadIdx.x;
    const int grp = t >> 3;
    const int sub = t & 7;
    const int e0r = grp << 3;
    const bool valid = e0r < N_EDGES;      // groups are 8-edge aligned (1e6 % 8 == 0)
    const int e0  = valid ? e0r : 0;

    // hoisted constants (amortized over 8 edges)
    const float4 w0 = *(const float4*)(W2 + sub * 8);
    const float4 w1 = *(const float4*)(W2 + sub * 8 + 4);
    const float w[8] = {w0.x, w0.y, w0.z, w0.w, w1.x, w1.y, w1.z, w1.w};
    const float b2v = __ldg(b2);

    // coalesced edge-index loads (one edge per lane)
    const int rv = __ldg(row + e0 + sub);
    const int cv = __ldg(col + e0 + sub);

    float res = 0.f;
#pragma unroll
    for (int g = 0; g < 8; g++) {
        const int r = __shfl_sync(0xffffffffu, rv, g, 8);
        const int c = __shfl_sync(0xffffffffu, cv, g, 8);

        const uint4 ur = *(const uint4*)(g_Ph + (size_t)r * PDIM + sub * 8);
        const uint4 vr = *(const uint4*)(g_Ph + (size_t)c * PDIM + NHID + sub * 8);
        const __half2* uh = (const __half2*)&ur;
        const __half2* vh = (const __half2*)&vr;

        float acc = 0.f;
#pragma unroll
        for (int i = 0; i < 4; i++) {
            const float2 uf = __half22float2(uh[i]);
            const float2 vf = __half22float2(vh[i]);
            const float h0 = fmaxf(uf.x + vf.x, 0.f);   // bias already in u
            const float h1 = fmaxf(uf.y + vf.y, 0.f);
            acc = fmaf(h0, w[2 * i],     acc);
            acc = fmaf(h1, w[2 * i + 1], acc);
        }
        acc += __shfl_xor_sync(0xffffffffu, acc, 4, 8);
        acc += __shfl_xor_sync(0xffffffffu, acc, 2, 8);
        acc += __shfl_xor_sync(0xffffffffu, acc, 1, 8);
        if (sub == g) res = acc + b2v;
    }

    if (valid) out[e0 + sub] = res;    // coalesced store of 8 results
}

// ---------------------------------------------------------------------------
extern "C" void kernel_launch(void* const* d_in, const int* in_sizes, int n_in,
                              void* d_out, int out_size) {
    const float* seq   = (const float*)d_in[0];
    const float* W_enc = (const float*)d_in[1];
    const float* b_enc = (const float*)d_in[2];
    const float* W1    = (const float*)d_in[3];
    const float* b1    = (const float*)d_in[4];
    const float* W2    = (const float*)d_in[5];
    const float* b2    = (const float*)d_in[6];
    const int*   rowi  = (const int*)d_in[7];
    const int*   coli  = (const int*)d_in[8];
    float* out = (float*)d_out;

    prep_kernel<<<128, 128>>>(W_enc, W1, b_enc, b1);

    cudaFuncSetAttribute(gemm_kernel, cudaFuncAttributeMaxDynamicSharedMemorySize, SM_TOTAL);
    gemm_kernel<<<(N_NODES + 63) / 64, 256, SM_TOTAL>>>(seq);

    // ONE thread per edge (8-lane groups cover 8 edges cooperatively)
    edge_kernel<<<(N_EDGES + 255) / 256, 256>>>(rowi, coli, W2, b2, out);
}